// round 2
// baseline (speedup 1.0000x reference)
#include <cuda_runtime.h>
#include <math.h>

#define HDIM 1024
#define NE   8
#define IDIM 4096
#define NT   4096         // B*S = 2*2048
#define TWO_T 8192

// ---------------- device scratch (allocation-free) ----------------
__device__ int   g_counts[NE];
__device__ int   g_off[NE + 1];
__device__ int   g_perm[NE * NT];     // token index per (expert, slot)
__device__ float g_pw[NE * NT];       // gate weight per (expert, slot)
__device__ float g_hmid[(size_t)TWO_T * IDIM];   // 134 MB intermediate

// ---------------- init ----------------
__global__ void init_kernel() {
    if (threadIdx.x < NE) g_counts[threadIdx.x] = 0;
}

// ---------------- router: 1 warp per token ----------------
__global__ void router_kernel(const float* __restrict__ x,
                              const float* __restrict__ gw,   // [H, E]
                              const float* __restrict__ gb) { // [E]
    int gtid = blockIdx.x * blockDim.x + threadIdx.x;
    int tok  = gtid >> 5;
    int lane = gtid & 31;
    if (tok >= NT) return;

    const float* xr = x + (size_t)tok * HDIM;
    float acc[NE];
#pragma unroll
    for (int e = 0; e < NE; e++) acc[e] = 0.f;

    for (int h = lane; h < HDIM; h += 32) {
        float xv = xr[h];
        const float* g = gw + (size_t)h * NE;
#pragma unroll
        for (int e = 0; e < NE; e++) acc[e] += xv * g[e];
    }
#pragma unroll
    for (int e = 0; e < NE; e++) {
#pragma unroll
        for (int o = 16; o > 0; o >>= 1)
            acc[e] += __shfl_xor_sync(0xffffffffu, acc[e], o);
    }

    if (lane == 0) {
        float l[NE];
        float mx = -1e30f;
#pragma unroll
        for (int e = 0; e < NE; e++) { l[e] = acc[e] + gb[e]; mx = fmaxf(mx, l[e]); }
        float s = 0.f;
#pragma unroll
        for (int e = 0; e < NE; e++) { l[e] = expf(l[e] - mx); s += l[e]; }
        // top-2 on probs (same order as logits); ties -> lowest index, matching top_k
        int i0 = 0; float p0 = l[0];
#pragma unroll
        for (int e = 1; e < NE; e++) if (l[e] > p0) { p0 = l[e]; i0 = e; }
        int i1 = -1; float p1 = -1.f;
#pragma unroll
        for (int e = 0; e < NE; e++) if (e != i0 && l[e] > p1) { p1 = l[e]; i1 = e; }
        p0 /= s; p1 /= s;
        float inv = 1.f / (p0 + p1 + 1e-6f);
        float w0 = p0 * inv, w1 = p1 * inv;

        int pos0 = atomicAdd(&g_counts[i0], 1);
        g_perm[i0 * NT + pos0] = tok;
        g_pw  [i0 * NT + pos0] = w0;
        int pos1 = atomicAdd(&g_counts[i1], 1);
        g_perm[i1 * NT + pos1] = tok;
        g_pw  [i1 * NT + pos1] = w1;
    }
}

// ---------------- offsets: exclusive scan over NE=8 ----------------
__global__ void offsets_kernel() {
    if (threadIdx.x == 0) {
        int o = 0;
        for (int e = 0; e < NE; e++) { g_off[e] = o; o += g_counts[e]; }
        g_off[NE] = o;
    }
}

// ---------------- tiled SGEMM params ----------------
#define BM 128
#define BN 128
#define BK 8
#define TM 8
#define TN 8

__device__ __forceinline__ float gelu_tanh(float v) {
    const float c = 0.7978845608028654f;   // sqrt(2/pi)
    float t = tanhf(c * (v + 0.044715f * v * v * v));
    return 0.5f * v * (1.f + t);
}

// GEMM1: hmid[off+m, n] = gelu( gather_x[m, :] @ W1[e][:, n] + b1[e][n] )
__global__ __launch_bounds__(256, 2)
void gemm1_kernel(const float* __restrict__ x,
                  const float* __restrict__ W1,   // [E, H, I]
                  const float* __restrict__ b1) { // [E, I]
    int e   = blockIdx.z;
    int cnt = g_counts[e];
    int m0  = blockIdx.y * BM;
    if (m0 >= cnt) return;
    int off = g_off[e];
    int n0  = blockIdx.x * BN;
    const float* Bp = W1 + (size_t)e * HDIM * IDIM;

    __shared__ float As[BK][BM];
    __shared__ float Bs[BK][BN];

    int tid  = threadIdx.x;
    int arow = tid >> 1;           // 0..127
    int acol = (tid & 1) * 4;      // 0 or 4
    int mrow = m0 + arow;
    int safem = mrow < cnt ? mrow : (cnt > 0 ? cnt - 1 : 0);
    int tokA = g_perm[e * NT + safem];
    const float* arow_ptr = x + (size_t)tokA * HDIM;

    int brow = tid >> 5;           // 0..7
    int bcol = (tid & 31) * 4;     // 0..124
    int tx = tid & 15, ty = tid >> 4;

    float acc[TM][TN];
#pragma unroll
    for (int i = 0; i < TM; i++)
#pragma unroll
        for (int j = 0; j < TN; j++) acc[i][j] = 0.f;

    for (int k0 = 0; k0 < HDIM; k0 += BK) {
        float4 av = *(const float4*)(arow_ptr + k0 + acol);
        As[acol + 0][arow] = av.x;
        As[acol + 1][arow] = av.y;
        As[acol + 2][arow] = av.z;
        As[acol + 3][arow] = av.w;
        float4 bv = *(const float4*)(Bp + (size_t)(k0 + brow) * IDIM + n0 + bcol);
        *(float4*)&Bs[brow][bcol] = bv;
        __syncthreads();
#pragma unroll
        for (int k = 0; k < BK; k++) {
            float a[TM], b[TN];
#pragma unroll
            for (int i = 0; i < TM; i++) a[i] = As[k][ty * TM + i];
#pragma unroll
            for (int j = 0; j < TN; j++) b[j] = Bs[k][tx * TN + j];
#pragma unroll
            for (int i = 0; i < TM; i++)
#pragma unroll
                for (int j = 0; j < TN; j++) acc[i][j] += a[i] * b[j];
        }
        __syncthreads();
    }

    const float* b1e = b1 + (size_t)e * IDIM + n0;
#pragma unroll
    for (int i = 0; i < TM; i++) {
        int m = m0 + ty * TM + i;
        if (m >= cnt) break;
        float* outr = g_hmid + (size_t)(off + m) * IDIM + n0;
#pragma unroll
        for (int j = 0; j < TN; j++) {
            int n = tx * TN + j;
            outr[n] = gelu_tanh(acc[i][j] + b1e[n]);
        }
    }
}

// GEMM2: out[tok, n] += w * ( hmid[off+m, :] @ W2[e][:, n] + b2[e][n] )
__global__ __launch_bounds__(256, 2)
void gemm2_kernel(const float* __restrict__ W2,   // [E, I, H]
                  const float* __restrict__ b2,   // [E, H]
                  float* __restrict__ out) {
    int e   = blockIdx.z;
    int cnt = g_counts[e];
    int m0  = blockIdx.y * BM;
    if (m0 >= cnt) return;
    int off = g_off[e];
    int n0  = blockIdx.x * BN;
    const float* Bp = W2 + (size_t)e * IDIM * HDIM;

    __shared__ float As[BK][BM];
    __shared__ float Bs[BK][BN];

    int tid  = threadIdx.x;
    int arow = tid >> 1;
    int acol = (tid & 1) * 4;
    int mrow = m0 + arow;
    int safem = mrow < cnt ? mrow : (cnt > 0 ? cnt - 1 : 0);
    const float* arow_ptr = g_hmid + (size_t)(off + safem) * IDIM;

    int brow = tid >> 5;
    int bcol = (tid & 31) * 4;
    int tx = tid & 15, ty = tid >> 4;

    float acc[TM][TN];
#pragma unroll
    for (int i = 0; i < TM; i++)
#pragma unroll
        for (int j = 0; j < TN; j++) acc[i][j] = 0.f;

    for (int k0 = 0; k0 < IDIM; k0 += BK) {
        float4 av = *(const float4*)(arow_ptr + k0 + acol);
        As[acol + 0][arow] = av.x;
        As[acol + 1][arow] = av.y;
        As[acol + 2][arow] = av.z;
        As[acol + 3][arow] = av.w;
        float4 bv = *(const float4*)(Bp + (size_t)(k0 + brow) * HDIM + n0 + bcol);
        *(float4*)&Bs[brow][bcol] = bv;
        __syncthreads();
#pragma unroll
        for (int k = 0; k < BK; k++) {
            float a[TM], b[TN];
#pragma unroll
            for (int i = 0; i < TM; i++) a[i] = As[k][ty * TM + i];
#pragma unroll
            for (int j = 0; j < TN; j++) b[j] = Bs[k][tx * TN + j];
#pragma unroll
            for (int i = 0; i < TM; i++)
#pragma unroll
                for (int j = 0; j < TN; j++) acc[i][j] += a[i] * b[j];
        }
        __syncthreads();
    }

    const float* b2e = b2 + (size_t)e * HDIM + n0;
#pragma unroll
    for (int i = 0; i < TM; i++) {
        int m = m0 + ty * TM + i;
        if (m >= cnt) break;
        int tok = g_perm[e * NT + m];
        float w = g_pw[e * NT + m];
        float* outr = out + (size_t)tok * HDIM + n0;
#pragma unroll
        for (int j = 0; j < TN; j++) {
            int n = tx * TN + j;
            atomicAdd(&outr[n], w * (acc[i][j] + b2e[n]));
        }
    }
}

// ---------------- launch ----------------
extern "C" void kernel_launch(void* const* d_in, const int* in_sizes, int n_in,
                              void* d_out, int out_size) {
    const float* x      = (const float*)d_in[0];   // [2,2048,1024]
    const float* gate_w = (const float*)d_in[1];   // [1024,8]
    const float* gate_b = (const float*)d_in[2];   // [8]
    const float* W1     = (const float*)d_in[3];   // [8,1024,4096]
    const float* b1     = (const float*)d_in[4];   // [8,4096]
    const float* W2     = (const float*)d_in[5];   // [8,4096,1024]
    const float* b2     = (const float*)d_in[6];   // [8,1024]
    float* out = (float*)d_out;                    // [2,2048,1024]

    cudaMemsetAsync(out, 0, (size_t)out_size * sizeof(float), 0);
    init_kernel<<<1, 32>>>();
    router_kernel<<<NT / 8, 256>>>(x, gate_w, gate_b);   // 8 warps/block = 8 tokens
    offsets_kernel<<<1, 32>>>();

    dim3 g1(IDIM / BN, (NT + BM - 1) / BM, NE);          // (32, 32, 8)
    gemm1_kernel<<<g1, 256>>>(x, W1, b1);

    dim3 g2(HDIM / BN, (NT + BM - 1) / BM, NE);          // (8, 32, 8)
    gemm2_kernel<<<g2, 256>>>(W2, b2, out);
}

// round 7
// speedup vs baseline: 2.6920x; 2.6920x over previous
#include <cuda_runtime.h>
#include <cuda_bf16.h>
#include <cstdint>
#include <math.h>

typedef unsigned int u32;

#define HDIM 1024
#define NE   8
#define IDIM 4096
#define NT   4096
#define TWO_T 8192

// ---------------- device scratch (allocation-free) ----------------
__device__ int   g_counts[NE];
__device__ int   g_off[NE + 1];
__device__ int   g_perm[NE * NT];
__device__ float g_pw[NE * NT];

__device__ float g_w1t[(size_t)NE * IDIM * HDIM];   // [e][n=I][k=H] fp32
__device__ float g_w2t[(size_t)NE * HDIM * IDIM];   // [e][n=H][k=I] fp32
__device__ float g_hmid[(size_t)TWO_T * IDIM];      // fp32 intermediate

// ---------------- init ----------------
__global__ void init_kernel() {
    if (threadIdx.x < NE) g_counts[threadIdx.x] = 0;
}

// ---------------- router: 1 warp per token ----------------
__global__ void router_kernel(const float* __restrict__ x,
                              const float* __restrict__ gw,
                              const float* __restrict__ gb) {
    int gtid = blockIdx.x * blockDim.x + threadIdx.x;
    int tok  = gtid >> 5;
    int lane = gtid & 31;
    if (tok >= NT) return;

    const float* xr = x + (size_t)tok * HDIM;
    float acc[NE];
#pragma unroll
    for (int e = 0; e < NE; e++) acc[e] = 0.f;
    for (int h = lane; h < HDIM; h += 32) {
        float xv = xr[h];
        const float* g = gw + (size_t)h * NE;
#pragma unroll
        for (int e = 0; e < NE; e++) acc[e] += xv * g[e];
    }
#pragma unroll
    for (int e = 0; e < NE; e++) {
#pragma unroll
        for (int o = 16; o > 0; o >>= 1)
            acc[e] += __shfl_xor_sync(0xffffffffu, acc[e], o);
    }
    if (lane == 0) {
        float l[NE];
        float mx = -1e30f;
#pragma unroll
        for (int e = 0; e < NE; e++) { l[e] = acc[e] + gb[e]; mx = fmaxf(mx, l[e]); }
        float s = 0.f;
#pragma unroll
        for (int e = 0; e < NE; e++) { l[e] = expf(l[e] - mx); s += l[e]; }
        int i0 = 0; float p0 = l[0];
#pragma unroll
        for (int e = 1; e < NE; e++) if (l[e] > p0) { p0 = l[e]; i0 = e; }
        int i1 = -1; float p1 = -1.f;
#pragma unroll
        for (int e = 0; e < NE; e++) if (e != i0 && l[e] > p1) { p1 = l[e]; i1 = e; }
        p0 /= s; p1 /= s;
        float inv = 1.f / (p0 + p1 + 1e-6f);
        int pos0 = atomicAdd(&g_counts[i0], 1);
        g_perm[i0 * NT + pos0] = tok;
        g_pw  [i0 * NT + pos0] = p0 * inv;
        int pos1 = atomicAdd(&g_counts[i1], 1);
        g_perm[i1 * NT + pos1] = tok;
        g_pw  [i1 * NT + pos1] = p1 * inv;
    }
}

__global__ void offsets_kernel() {
    if (threadIdx.x == 0) {
        int o = 0;
        for (int e = 0; e < NE; e++) { g_off[e] = o; o += g_counts[e]; }
        g_off[NE] = o;
    }
}

// ---------------- fp32 weight transpose: in [e][K][N] -> out [e][N][K] ----------------
// WSEL=1 -> g_w1t, WSEL=2 -> g_w2t (globals referenced directly, no symbol lookup)
template <int WSEL>
__global__ void transpose_w_kernel(const float* __restrict__ in, int K, int N) {
    __shared__ float t[32][33];
    float* outp = (WSEL == 1) ? g_w1t : g_w2t;
    int e = blockIdx.z;
    const float* ine = in + (size_t)e * K * N;
    float* oute = outp + (size_t)e * N * K;
    int n0 = blockIdx.x * 32, k0 = blockIdx.y * 32;
    int tx = threadIdx.x, ty = threadIdx.y;  // (32, 8)
#pragma unroll
    for (int i = 0; i < 4; i++)
        t[ty + i * 8][tx] = ine[(size_t)(k0 + ty + i * 8) * N + n0 + tx];
    __syncthreads();
#pragma unroll
    for (int i = 0; i < 4; i++) {
        int n = n0 + ty + i * 8;
        int k = k0 + tx;
        oute[(size_t)n * K + k] = t[tx][ty + i * 8];
    }
}

// ---------------- tensor-core grouped GEMM (on-the-fly split-bf16 x3) ----------------
#define RS 20                 // u32 per smem row (16 data + 4 pad)
#define SM_MAT 2560           // 128 * RS
// 4 matrices (A hi/lo, B hi/lo): 40960 bytes static shared

__device__ __forceinline__ void mma16816(float* c, const u32* a, const u32* b) {
    asm volatile(
        "mma.sync.aligned.m16n8k16.row.col.f32.bf16.bf16.f32 "
        "{%0,%1,%2,%3},{%4,%5,%6,%7},{%8,%9},{%0,%1,%2,%3};"
        : "+f"(c[0]), "+f"(c[1]), "+f"(c[2]), "+f"(c[3])
        : "r"(a[0]), "r"(a[1]), "r"(a[2]), "r"(a[3]), "r"(b[0]), "r"(b[1]));
}

__device__ __forceinline__ float gelu_tanh(float v) {
    const float c = 0.7978845608028654f;
    float t = tanhf(c * (v + 0.044715f * v * v * v));
    return 0.5f * v * (1.f + t);
}

// split a float4 (4 consecutive k values) into 2 packed-hi u32 and 2 packed-lo u32
__device__ __forceinline__ void split_pack4(float4 v, u32& h0, u32& h1, u32& l0, u32& l1) {
    __nv_bfloat16 a = __float2bfloat16(v.x);
    __nv_bfloat16 b = __float2bfloat16(v.y);
    __nv_bfloat16 c = __float2bfloat16(v.z);
    __nv_bfloat16 d = __float2bfloat16(v.w);
    __nv_bfloat16 ra = __float2bfloat16(v.x - __bfloat162float(a));
    __nv_bfloat16 rb = __float2bfloat16(v.y - __bfloat162float(b));
    __nv_bfloat16 rc = __float2bfloat16(v.z - __bfloat162float(c));
    __nv_bfloat16 rd = __float2bfloat16(v.w - __bfloat162float(d));
    __nv_bfloat162 ph0 = __halves2bfloat162(a, b);   // low half = k (lower)
    __nv_bfloat162 ph1 = __halves2bfloat162(c, d);
    __nv_bfloat162 pl0 = __halves2bfloat162(ra, rb);
    __nv_bfloat162 pl1 = __halves2bfloat162(rc, rd);
    h0 = *reinterpret_cast<u32*>(&ph0);
    h1 = *reinterpret_cast<u32*>(&ph1);
    l0 = *reinterpret_cast<u32*>(&pl0);
    l1 = *reinterpret_cast<u32*>(&pl1);
}

// EPI=0: GEMM1 (A = gathered x fp32, B = g_w1t fp32) -> gelu -> g_hmid fp32
// EPI=1: GEMM2 (A = g_hmid fp32,     B = g_w2t fp32) -> bias, gate-w, atomic out
template <int EPI>
__global__ __launch_bounds__(256, 1)
void moe_gemm(const float* __restrict__ xin,
              const float* __restrict__ bias, float* __restrict__ outp,
              int Kdim, int Ndim) {
    __shared__ u32 smu[4 * SM_MAT];
    const int e   = blockIdx.z;
    const int cnt = g_counts[e];
    const int m0  = blockIdx.y * 128;
    if (m0 >= cnt) return;
    const int off = g_off[e];
    const int n0  = blockIdx.x * 128;
    const int tid = threadIdx.x;

    // ---- loader: thread handles row r = tid>>1, k-half h2 = tid&1 (16 floats each)
    const int r  = tid >> 1;
    const int h2 = tid & 1;
    const int kbase = h2 * 16;
    int am = m0 + r; if (am > cnt - 1) am = cnt - 1;
    const float* af;
    if (EPI == 0) {
        int tok = g_perm[e * NT + am];
        af = xin + (size_t)tok * Kdim;
    } else {
        af = g_hmid + (size_t)(off + am) * Kdim;
    }
    const float* wt = (EPI == 0) ? g_w1t : g_w2t;
    const float* bf = wt + ((size_t)e * Ndim + n0 + r) * (size_t)Kdim;

    const int lane = tid & 31, warp = tid >> 5;
    const int g  = lane >> 2, tq = lane & 3;
    const int mw = (warp & 1) * 64, nw = (warp >> 1) * 32;

    float acc[4][4][4];
#pragma unroll
    for (int a = 0; a < 4; a++)
#pragma unroll
        for (int b = 0; b < 4; b++)
#pragma unroll
            for (int cc = 0; cc < 4; cc++) acc[a][b][cc] = 0.f;

    float4 pa[4], pb[4];

#define LOADG(k0)                                                            \
    {                                                                        \
        _Pragma("unroll") for (int j = 0; j < 4; j++) {                      \
            pa[j] = *(const float4*)(af + (k0) + kbase + j * 4);             \
            pb[j] = *(const float4*)(bf + (k0) + kbase + j * 4);             \
        }                                                                    \
    }
#define STORES()                                                             \
    {                                                                        \
        u32 ha[8], la[8], hb[8], lb[8];                                      \
        _Pragma("unroll") for (int j = 0; j < 4; j++) {                      \
            split_pack4(pa[j], ha[j*2], ha[j*2+1], la[j*2], la[j*2+1]);      \
            split_pack4(pb[j], hb[j*2], hb[j*2+1], lb[j*2], lb[j*2+1]);      \
        }                                                                    \
        int sb = r * RS + h2 * 8;                                            \
        *(uint4*)&smu[0 * SM_MAT + sb]     = make_uint4(ha[0], ha[1], ha[2], ha[3]); \
        *(uint4*)&smu[0 * SM_MAT + sb + 4] = make_uint4(ha[4], ha[5], ha[6], ha[7]); \
        *(uint4*)&smu[1 * SM_MAT + sb]     = make_uint4(la[0], la[1], la[2], la[3]); \
        *(uint4*)&smu[1 * SM_MAT + sb + 4] = make_uint4(la[4], la[5], la[6], la[7]); \
        *(uint4*)&smu[2 * SM_MAT + sb]     = make_uint4(hb[0], hb[1], hb[2], hb[3]); \
        *(uint4*)&smu[2 * SM_MAT + sb + 4] = make_uint4(hb[4], hb[5], hb[6], hb[7]); \
        *(uint4*)&smu[3 * SM_MAT + sb]     = make_uint4(lb[0], lb[1], lb[2], lb[3]); \
        *(uint4*)&smu[3 * SM_MAT + sb + 4] = make_uint4(lb[4], lb[5], lb[6], lb[7]); \
    }

    const u32* Ah = smu;
    const u32* Al = smu + SM_MAT;
    const u32* Bh = smu + 2 * SM_MAT;
    const u32* Bl = smu + 3 * SM_MAT;

    const int nch = Kdim / 32;
    LOADG(0);
    for (int c = 0; c < nch; c++) {
        if (c > 0) __syncthreads();
        STORES();
        __syncthreads();
        if (c + 1 < nch) LOADG((c + 1) * 32);
#pragma unroll
        for (int ks = 0; ks < 2; ks++) {
            const int ku = ks * 8 + tq;
            u32 ah[4][4], al[4][4], bh[4][2], bl[4][2];
#pragma unroll
            for (int mt = 0; mt < 4; mt++) {
                int base = (mw + mt * 16 + g) * RS + ku;
                ah[mt][0] = Ah[base];          ah[mt][1] = Ah[base + 8 * RS];
                ah[mt][2] = Ah[base + 4];      ah[mt][3] = Ah[base + 8 * RS + 4];
                al[mt][0] = Al[base];          al[mt][1] = Al[base + 8 * RS];
                al[mt][2] = Al[base + 4];      al[mt][3] = Al[base + 8 * RS + 4];
            }
#pragma unroll
            for (int nt = 0; nt < 4; nt++) {
                int bb = (nw + nt * 8 + g) * RS + ku;
                bh[nt][0] = Bh[bb];  bh[nt][1] = Bh[bb + 4];
                bl[nt][0] = Bl[bb];  bl[nt][1] = Bl[bb + 4];
            }
#pragma unroll
            for (int mt = 0; mt < 4; mt++)
#pragma unroll
                for (int nt = 0; nt < 4; nt++) {
                    mma16816(acc[mt][nt], ah[mt], bh[nt]);
                    mma16816(acc[mt][nt], ah[mt], bl[nt]);
                    mma16816(acc[mt][nt], al[mt], bh[nt]);
                }
        }
    }
#undef LOADG
#undef STORES

    // ---- epilogue
#pragma unroll
    for (int mt = 0; mt < 4; mt++) {
#pragma unroll
        for (int half = 0; half < 2; half++) {
            int rr = m0 + mw + mt * 16 + g + half * 8;   // local row in expert
            if (rr >= cnt) continue;
            if (EPI == 0) {
                size_t orow = (size_t)(off + rr) * Ndim;
#pragma unroll
                for (int nt = 0; nt < 4; nt++) {
                    int cc = n0 + nw + nt * 8 + tq * 2;
                    float v0 = gelu_tanh(acc[mt][nt][half * 2 + 0] + bias[(size_t)e * Ndim + cc]);
                    float v1 = gelu_tanh(acc[mt][nt][half * 2 + 1] + bias[(size_t)e * Ndim + cc + 1]);
                    *(float2*)&g_hmid[orow + cc] = make_float2(v0, v1);
                }
            } else {
                int tok = g_perm[e * NT + rr];
                float w = g_pw[e * NT + rr];
                float* od = outp + (size_t)tok * Ndim;
#pragma unroll
                for (int nt = 0; nt < 4; nt++) {
                    int cc = n0 + nw + nt * 8 + tq * 2;
                    float v0 = acc[mt][nt][half * 2 + 0] + bias[(size_t)e * Ndim + cc];
                    float v1 = acc[mt][nt][half * 2 + 1] + bias[(size_t)e * Ndim + cc + 1];
                    atomicAdd(od + cc, w * v0);
                    atomicAdd(od + cc + 1, w * v1);
                }
            }
        }
    }
}

// ---------------- launch ----------------
extern "C" void kernel_launch(void* const* d_in, const int* in_sizes, int n_in,
                              void* d_out, int out_size) {
    const float* x      = (const float*)d_in[0];
    const float* gate_w = (const float*)d_in[1];
    const float* gate_b = (const float*)d_in[2];
    const float* W1     = (const float*)d_in[3];   // [8,1024,4096]
    const float* b1     = (const float*)d_in[4];
    const float* W2     = (const float*)d_in[5];   // [8,4096,1024]
    const float* b2     = (const float*)d_in[6];
    float* out = (float*)d_out;

    cudaMemsetAsync(out, 0, (size_t)out_size * sizeof(float), 0);
    init_kernel<<<1, 32>>>();
    router_kernel<<<NT / 8, 256>>>(x, gate_w, gate_b);
    offsets_kernel<<<1, 32>>>();

    // fp32 weight transposes into device globals (no symbol lookups anywhere)
    dim3 tb(32, 8);
    transpose_w_kernel<1><<<dim3(IDIM / 32, HDIM / 32, NE), tb>>>(W1, HDIM, IDIM);
    transpose_w_kernel<2><<<dim3(HDIM / 32, IDIM / 32, NE), tb>>>(W2, IDIM, HDIM);

    // GEMM1: [cnt x 1024] @ [1024 x 4096] -> g_hmid
    dim3 g1(IDIM / 128, NT / 128, NE);
    moe_gemm<0><<<g1, 256>>>(x, b1, nullptr, HDIM, IDIM);

    // GEMM2: [cnt x 4096] @ [4096 x 1024] -> out (atomic combine)
    dim3 g2(HDIM / 128, NT / 128, NE);
    moe_gemm<1><<<g2, 256>>>(nullptr, b2, out, IDIM, HDIM);
}

// round 8
// speedup vs baseline: 3.1049x; 1.1534x over previous
#include <cuda_runtime.h>
#include <cuda_bf16.h>
#include <cstdint>
#include <math.h>

typedef unsigned int u32;

#define HDIM 1024
#define NE   8
#define IDIM 4096
#define NT   4096
#define TWO_T 8192

// ---------------- device scratch (allocation-free; ONLY referenced inside kernels) ----
__device__ int   g_counts[NE];
__device__ int   g_off[NE + 1];
__device__ int   g_perm[NE * NT];
__device__ float g_pw[NE * NT];

__device__ __nv_bfloat16 g_xh[(size_t)NT * HDIM];
__device__ __nv_bfloat16 g_xl[(size_t)NT * HDIM];
__device__ __nv_bfloat16 g_w1h[(size_t)NE * IDIM * HDIM];  // [e][n=I][k=H]
__device__ __nv_bfloat16 g_w1l[(size_t)NE * IDIM * HDIM];
__device__ __nv_bfloat16 g_w2h[(size_t)NE * HDIM * IDIM];  // [e][n=H][k=I]
__device__ __nv_bfloat16 g_w2l[(size_t)NE * HDIM * IDIM];
__device__ __nv_bfloat16 g_hh[(size_t)TWO_T * IDIM];
__device__ __nv_bfloat16 g_hl[(size_t)TWO_T * IDIM];

__device__ __forceinline__ void split2(float v, __nv_bfloat16& h, __nv_bfloat16& l) {
    h = __float2bfloat16(v);
    l = __float2bfloat16(v - __bfloat162float(h));
}

// ---------------- init ----------------
__global__ void init_kernel() {
    if (threadIdx.x < NE) g_counts[threadIdx.x] = 0;
}

// ---------------- router: 1 warp per token ----------------
__global__ void router_kernel(const float* __restrict__ x,
                              const float* __restrict__ gw,
                              const float* __restrict__ gb) {
    int gtid = blockIdx.x * blockDim.x + threadIdx.x;
    int tok  = gtid >> 5;
    int lane = gtid & 31;
    if (tok >= NT) return;

    const float* xr = x + (size_t)tok * HDIM;
    float acc[NE];
#pragma unroll
    for (int e = 0; e < NE; e++) acc[e] = 0.f;
    for (int h = lane; h < HDIM; h += 32) {
        float xv = xr[h];
        const float* g = gw + (size_t)h * NE;
#pragma unroll
        for (int e = 0; e < NE; e++) acc[e] += xv * g[e];
    }
#pragma unroll
    for (int e = 0; e < NE; e++) {
#pragma unroll
        for (int o = 16; o > 0; o >>= 1)
            acc[e] += __shfl_xor_sync(0xffffffffu, acc[e], o);
    }
    if (lane == 0) {
        float l[NE];
        float mx = -1e30f;
#pragma unroll
        for (int e = 0; e < NE; e++) { l[e] = acc[e] + gb[e]; mx = fmaxf(mx, l[e]); }
        float s = 0.f;
#pragma unroll
        for (int e = 0; e < NE; e++) { l[e] = expf(l[e] - mx); s += l[e]; }
        int i0 = 0; float p0 = l[0];
#pragma unroll
        for (int e = 1; e < NE; e++) if (l[e] > p0) { p0 = l[e]; i0 = e; }
        int i1 = -1; float p1 = -1.f;
#pragma unroll
        for (int e = 0; e < NE; e++) if (e != i0 && l[e] > p1) { p1 = l[e]; i1 = e; }
        p0 /= s; p1 /= s;
        float inv = 1.f / (p0 + p1 + 1e-6f);
        int pos0 = atomicAdd(&g_counts[i0], 1);
        g_perm[i0 * NT + pos0] = tok;
        g_pw  [i0 * NT + pos0] = p0 * inv;
        int pos1 = atomicAdd(&g_counts[i1], 1);
        g_perm[i1 * NT + pos1] = tok;
        g_pw  [i1 * NT + pos1] = p1 * inv;
    }
}

__global__ void offsets_kernel() {
    if (threadIdx.x == 0) {
        int o = 0;
        for (int e = 0; e < NE; e++) { g_off[e] = o; o += g_counts[e]; }
        g_off[NE] = o;
    }
}

// ---------------- prepasses (outputs selected INSIDE the kernel) ----------------
__global__ void split_x_kernel(const float* __restrict__ x) {
    size_t i = (size_t)blockIdx.x * blockDim.x + threadIdx.x;
    if (i < (size_t)NT * HDIM) split2(x[i], g_xh[i], g_xl[i]);
}

// in [e][K][N] fp32 -> out [e][N][K] bf16 hi/lo.  WSEL=1 -> w1, 2 -> w2
template <int WSEL>
__global__ void transpose_split_w(const float* __restrict__ in, int K, int N) {
    __shared__ float t[32][33];
    __nv_bfloat16* oh = (WSEL == 1) ? g_w1h : g_w2h;
    __nv_bfloat16* ol = (WSEL == 1) ? g_w1l : g_w2l;
    int e = blockIdx.z;
    const float* ine = in + (size_t)e * K * N;
    size_t ob = (size_t)e * N * K;
    int n0 = blockIdx.x * 32, k0 = blockIdx.y * 32;
    int tx = threadIdx.x, ty = threadIdx.y;  // (32, 8)
#pragma unroll
    for (int i = 0; i < 4; i++)
        t[ty + i * 8][tx] = ine[(size_t)(k0 + ty + i * 8) * N + n0 + tx];
    __syncthreads();
#pragma unroll
    for (int i = 0; i < 4; i++) {
        int n = n0 + ty + i * 8;
        int k = k0 + tx;
        __nv_bfloat16 h, l; split2(t[tx][ty + i * 8], h, l);
        oh[ob + (size_t)n * K + k] = h;
        ol[ob + (size_t)n * K + k] = l;
    }
}

// ---------------- tensor-core grouped GEMM (split-bf16 x3, cp.async pipelined) -------
#define RS 20                 // u32 per smem row (16 data + 4 pad)
#define SM_MAT 2560           // 128 * RS
#define SMEM_BYTES (8 * SM_MAT * 4)   // 4 matrices x 2 buffers = 80KB

__device__ __forceinline__ void cp16(u32 dst, const void* src) {
    asm volatile("cp.async.cg.shared.global [%0], [%1], 16;" :: "r"(dst), "l"(src));
}

__device__ __forceinline__ void mma16816(float* c, const u32* a, const u32* b) {
    asm volatile(
        "mma.sync.aligned.m16n8k16.row.col.f32.bf16.bf16.f32 "
        "{%0,%1,%2,%3},{%4,%5,%6,%7},{%8,%9},{%0,%1,%2,%3};"
        : "+f"(c[0]), "+f"(c[1]), "+f"(c[2]), "+f"(c[3])
        : "r"(a[0]), "r"(a[1]), "r"(a[2]), "r"(a[3]), "r"(b[0]), "r"(b[1]));
}

__device__ __forceinline__ float gelu_tanh(float v) {
    const float c = 0.7978845608028654f;
    float t = tanhf(c * (v + 0.044715f * v * v * v));
    return 0.5f * v * (1.f + t);
}

// EPI=0: GEMM1 (A = gathered x hi/lo, B = w1 hi/lo) -> gelu -> g_hh/g_hl
// EPI=1: GEMM2 (A = g_hh/g_hl,        B = w2 hi/lo) -> bias, gate-w, atomic out
template <int EPI>
__global__ __launch_bounds__(256, 1)
void moe_gemm(const float* __restrict__ bias, float* __restrict__ outp,
              int Kdim, int Ndim) {
    extern __shared__ u32 smu[];
    const int e   = blockIdx.z;
    const int cnt = g_counts[e];
    const int m0  = blockIdx.y * 128;
    if (m0 >= cnt) return;
    const int off = g_off[e];
    const int n0  = blockIdx.x * 128;
    const int tid = threadIdx.x;

    // ---- loader: row = tid>>1, 2 x 16B segments per matrix per thread
    const int arow = tid >> 1;
    const int aseg = (tid & 1) * 2;
    int am = m0 + arow; if (am > cnt - 1) am = cnt - 1;
    const __nv_bfloat16 *agh, *agl, *bgh, *bgl;
    if (EPI == 0) {
        int tok = g_perm[e * NT + am];
        agh = g_xh + (size_t)tok * Kdim;
        agl = g_xl + (size_t)tok * Kdim;
        bgh = g_w1h + ((size_t)e * Ndim + n0 + arow) * (size_t)Kdim;
        bgl = g_w1l + ((size_t)e * Ndim + n0 + arow) * (size_t)Kdim;
    } else {
        agh = g_hh + (size_t)(off + am) * Kdim;
        agl = g_hl + (size_t)(off + am) * Kdim;
        bgh = g_w2h + ((size_t)e * Ndim + n0 + arow) * (size_t)Kdim;
        bgl = g_w2l + ((size_t)e * Ndim + n0 + arow) * (size_t)Kdim;
    }

    const u32 smbase = (u32)__cvta_generic_to_shared(smu);

#define ISSUE(buf, k0)                                                                       \
    {                                                                                        \
        _Pragma("unroll") for (int s = 0; s < 2; s++) {                                      \
            int sg = aseg + s;                                                               \
            cp16(smbase + 4u * (((buf) * 2 + 0) * SM_MAT + arow * RS + sg * 4), agh + (k0) + sg * 8); \
            cp16(smbase + 4u * (((buf) * 2 + 1) * SM_MAT + arow * RS + sg * 4), agl + (k0) + sg * 8); \
            cp16(smbase + 4u * ((4 + (buf) * 2 + 0) * SM_MAT + arow * RS + sg * 4), bgh + (k0) + sg * 8); \
            cp16(smbase + 4u * ((4 + (buf) * 2 + 1) * SM_MAT + arow * RS + sg * 4), bgl + (k0) + sg * 8); \
        }                                                                                    \
        asm volatile("cp.async.commit_group;");                                              \
    }

    const int lane = tid & 31, warp = tid >> 5;
    const int g  = lane >> 2, tq = lane & 3;
    const int mw = (warp & 1) * 64, nw = (warp >> 1) * 32;

    float acc[4][4][4];
#pragma unroll
    for (int a = 0; a < 4; a++)
#pragma unroll
        for (int b = 0; b < 4; b++)
#pragma unroll
            for (int cc = 0; cc < 4; cc++) acc[a][b][cc] = 0.f;

    const int nch = Kdim / 32;
    ISSUE(0, 0);
    for (int c = 0; c < nch; c++) {
        int cur = c & 1;
        if (c + 1 < nch) {
            ISSUE(cur ^ 1, (c + 1) * 32);
            asm volatile("cp.async.wait_group 1;");
        } else {
            asm volatile("cp.async.wait_group 0;");
        }
        __syncthreads();
        const u32* Ah = smu + (cur * 2 + 0) * SM_MAT;
        const u32* Al = smu + (cur * 2 + 1) * SM_MAT;
        const u32* Bh = smu + (4 + cur * 2 + 0) * SM_MAT;
        const u32* Bl = smu + (4 + cur * 2 + 1) * SM_MAT;
#pragma unroll
        for (int ks = 0; ks < 2; ks++) {
            const int ku = ks * 8 + tq;
            u32 ah[4][4], al[4][4], bh[4][2], bl[4][2];
#pragma unroll
            for (int mt = 0; mt < 4; mt++) {
                int base = (mw + mt * 16 + g) * RS + ku;
                ah[mt][0] = Ah[base];          ah[mt][1] = Ah[base + 8 * RS];
                ah[mt][2] = Ah[base + 4];      ah[mt][3] = Ah[base + 8 * RS + 4];
                al[mt][0] = Al[base];          al[mt][1] = Al[base + 8 * RS];
                al[mt][2] = Al[base + 4];      al[mt][3] = Al[base + 8 * RS + 4];
            }
#pragma unroll
            for (int nt = 0; nt < 4; nt++) {
                int bb = (nw + nt * 8 + g) * RS + ku;
                bh[nt][0] = Bh[bb];  bh[nt][1] = Bh[bb + 4];
                bl[nt][0] = Bl[bb];  bl[nt][1] = Bl[bb + 4];
            }
#pragma unroll
            for (int mt = 0; mt < 4; mt++)
#pragma unroll
                for (int nt = 0; nt < 4; nt++) {
                    mma16816(acc[mt][nt], ah[mt], bh[nt]);
                    mma16816(acc[mt][nt], ah[mt], bl[nt]);
                    mma16816(acc[mt][nt], al[mt], bh[nt]);
                }
        }
        __syncthreads();
    }
#undef ISSUE

    // ---- epilogue
#pragma unroll
    for (int mt = 0; mt < 4; mt++) {
#pragma unroll
        for (int half = 0; half < 2; half++) {
            int r = m0 + mw + mt * 16 + g + half * 8;
            if (r >= cnt) continue;
            if (EPI == 0) {
                size_t orow = (size_t)(off + r) * Ndim;
#pragma unroll
                for (int nt = 0; nt < 4; nt++) {
                    int cc = n0 + nw + nt * 8 + tq * 2;
                    float v0 = gelu_tanh(acc[mt][nt][half * 2 + 0] + bias[(size_t)e * Ndim + cc]);
                    float v1 = gelu_tanh(acc[mt][nt][half * 2 + 1] + bias[(size_t)e * Ndim + cc + 1]);
                    __nv_bfloat16 h0, l0, h1, l1;
                    split2(v0, h0, l0); split2(v1, h1, l1);
                    __nv_bfloat162 ph; ph.x = h0; ph.y = h1;
                    __nv_bfloat162 pl; pl.x = l0; pl.y = l1;
                    *reinterpret_cast<__nv_bfloat162*>(&g_hh[orow + cc]) = ph;
                    *reinterpret_cast<__nv_bfloat162*>(&g_hl[orow + cc]) = pl;
                }
            } else {
                int tok = g_perm[e * NT + r];
                float w = g_pw[e * NT + r];
                float* od = outp + (size_t)tok * Ndim;
#pragma unroll
                for (int nt = 0; nt < 4; nt++) {
                    int cc = n0 + nw + nt * 8 + tq * 2;
                    float v0 = acc[mt][nt][half * 2 + 0] + bias[(size_t)e * Ndim + cc];
                    float v1 = acc[mt][nt][half * 2 + 1] + bias[(size_t)e * Ndim + cc + 1];
                    atomicAdd(od + cc, w * v0);
                    atomicAdd(od + cc + 1, w * v1);
                }
            }
        }
    }
}

// ---------------- launch ----------------
extern "C" void kernel_launch(void* const* d_in, const int* in_sizes, int n_in,
                              void* d_out, int out_size) {
    const float* x      = (const float*)d_in[0];
    const float* gate_w = (const float*)d_in[1];
    const float* gate_b = (const float*)d_in[2];
    const float* W1     = (const float*)d_in[3];   // [8,1024,4096]
    const float* b1     = (const float*)d_in[4];
    const float* W2     = (const float*)d_in[5];   // [8,4096,1024]
    const float* b2     = (const float*)d_in[6];
    float* out = (float*)d_out;

    cudaFuncSetAttribute(moe_gemm<0>, cudaFuncAttributeMaxDynamicSharedMemorySize, SMEM_BYTES);
    cudaFuncSetAttribute(moe_gemm<1>, cudaFuncAttributeMaxDynamicSharedMemorySize, SMEM_BYTES);

    cudaMemsetAsync(out, 0, (size_t)out_size * sizeof(float), 0);
    init_kernel<<<1, 32>>>();
    router_kernel<<<NT / 8, 256>>>(x, gate_w, gate_b);
    offsets_kernel<<<1, 32>>>();

    split_x_kernel<<<(NT * HDIM + 255) / 256, 256>>>(x);
    dim3 tb(32, 8);
    transpose_split_w<1><<<dim3(IDIM / 32, HDIM / 32, NE), tb>>>(W1, HDIM, IDIM);
    transpose_split_w<2><<<dim3(HDIM / 32, IDIM / 32, NE), tb>>>(W2, IDIM, HDIM);

    dim3 g1(IDIM / 128, NT / 128, NE);
    moe_gemm<0><<<g1, 256, SMEM_BYTES>>>(b1, nullptr, HDIM, IDIM);

    dim3 g2(HDIM / 128, NT / 128, NE);
    moe_gemm<1><<<g2, 256, SMEM_BYTES>>>(b2, out, IDIM, HDIM);
}